// round 13
// baseline (speedup 1.0000x reference)
#include <cuda_runtime.h>

// DeepSurvLoss, N=16384 — ONE cluster of 8 CTAs x 1024 threads.
// HW cluster barriers (release/acquire + CCTL.IVALL) replace the software
// atomic grid barrier; final reduce via g_part + second cluster.sync
// replaces the atomic done-counter tail.
// bucket = floor(T*2^14): exact & monotone for T in [0,1).
// has_risk[i] <=> S_i > 0 exactly (all pe > 0; empty suffixes exact 0).

#define NB    16384
#define NBLK  8
#define TPB   1024
#define BPC   2048            // buckets (and elements) per CTA
#define CAP   16              // slots per bucket (Poisson(1): safe)
#define RPAD  64              // 256B stride per rtot counter
#define NRT   64              // rtot counters, 256 buckets each
#define EPSF  1e-6f

struct __align__(256) Bucket {
    int    cnt;               // byte 0
    float  bsum;              // byte 4
    float2 slot[CAP];         // bytes 8..136
    int    pad[30];
};

__device__ Bucket g_bkt[NB];                       // headers reset by owner
__device__ __align__(256) float g_rtot[NRT * RPAD];// reset post-sync#2
__device__ float2 g_part[NBLK];                    // written before read each call

__device__ __forceinline__ int bucket_of(float t) {
    int b = (int)(t * 16384.0f);                   // *2^14: exact, monotone
    return b > (NB - 1) ? (NB - 1) : b;
}

#define CLUSTER_SYNC() do { \
    asm volatile("barrier.cluster.arrive.aligned;" ::: "memory"); \
    asm volatile("barrier.cluster.wait.aligned;"   ::: "memory"); \
} while (0)

__global__ void __launch_bounds__(TPB, 1) __cluster_dims__(NBLK, 1, 1)
k_all(const float* __restrict__ P_risk, const float* __restrict__ T,
      const int* __restrict__ E, float* __restrict__ out)
{
    __shared__ float s_ws[32];
    __shared__ float s_rn[32], s_rd[32];
    __shared__ float s_above;

    const int tid  = threadIdx.x, blk = blockIdx.x;
    const int lane = tid & 31,    w   = tid >> 5;
    const int range_lo = blk * BPC;

    // ---- Phase 1: two elements per thread ----
    #pragma unroll
    for (int e = 0; e < 2; e++) {
        const int   i  = range_lo + e * TPB + tid;      // coalesced
        const float t  = T[i];
        const int   Ei = E[i];
        const float pe = __expf(P_risk[i]);
        const int   b  = bucket_of(t);
        Bucket* bk = &g_bkt[b];
        atomicAdd(&bk->bsum, pe);                       // line-private RED
        atomicAdd(&g_rtot[(b >> 8) * RPAD], pe);        // padded RED
        const int pos = atomicAdd(&bk->cnt, 1);
        if (pos < CAP)
            bk->slot[pos] = make_float2(t, Ei ? -pe : pe);
    }

    CLUSTER_SYNC();                                     // HW barrier #1

    // ---- Phase 2: headers + s_above + suffix scan (2 buckets/thread) ----
    // Thread t owns local buckets lb0 = 2046-2t, lb1 = 2047-2t; the reversed
    // pair scan directly yields strictly-greater suffixes for both.
    const int lb1 = (BPC - 1) - 2 * tid;
    const int gb0 = range_lo + lb1 - 1;
    const int2 h0 = *(const int2*)&g_bkt[gb0];          // (cnt, bsum) bitcast
    const int2 h1 = *(const int2*)&g_bkt[gb0 + 1];
    const int   c0  = min(h0.x, CAP), c1 = min(h1.x, CAP);
    const float bs0 = __int_as_float(h0.y);
    const float bs1 = __int_as_float(h1.y);

    if (w == 0) {                                       // s_above, lane-parallel
        const int thr = (blk + 1) * (BPC / 256);        // counters above my range
        float v = 0.f;
        if (lane      >= thr) v += g_rtot[lane * RPAD];
        if (lane + 32 >= thr) v += g_rtot[(lane + 32) * RPAD];
        #pragma unroll
        for (int o = 16; o; o >>= 1)
            v += __shfl_xor_sync(0xffffffffu, v, o);
        if (lane == 0) s_above = v;
    }

    const float s = bs0 + bs1;                          // reversed-pair sum
    float incl = s;
    #pragma unroll
    for (int o = 1; o < 32; o <<= 1) {
        float v = __shfl_up_sync(0xffffffffu, incl, o);
        if (lane >= o) incl += v;
    }
    if (lane == 31) s_ws[w] = incl;
    __syncthreads();
    if (w == 0) {
        float v = s_ws[lane], iv = v;
        #pragma unroll
        for (int o = 1; o < 32; o <<= 1) {
            float u = __shfl_up_sync(0xffffffffu, iv, o);
            if (lane >= o) iv += u;
        }
        s_ws[lane] = iv - v;                            // exclusive warp bases
    }
    __syncthreads();
    const float base = s_ws[w] + (incl - s);            // sum of buckets > lb1
    const float suf1 = s_above + base;
    const float suf0 = suf1 + bs1;                      // + bucket lb1 itself

    // ---- Phase 3: loss for my two buckets ----
    float num = 0.f, den = 0.f;
    #pragma unroll
    for (int q = 0; q < 2; q++) {
        const int    c   = q ? c1 : c0;
        const float  suf = q ? suf1 : suf0;
        const float2* sl = g_bkt[gb0 + q].slot;
        for (int e1 = 0; e1 < c; e1++) {
            float2 v1 = sl[e1];
            if (v1.y < 0.f) {                           // E == 1
                float S = suf;
                for (int e2 = 0; e2 < c; e2++) {
                    if (e2 == e1) continue;
                    float2 v2 = sl[e2];
                    if (v2.x > v1.x) S += fabsf(v2.y);  // strict, exact
                }
                if (S > 0.f) {                          // has_risk (exact)
                    float pt = -v1.y / (S + EPSF);
                    num += __logf(fmaxf(pt, EPSF));     // upper clip: no-op
                    den += 1.f;
                }
            }
        }
    }
    // owner resets its own headers (only owner ever reads them)
    *(int2*)&g_bkt[gb0]     = make_int2(0, 0);
    *(int2*)&g_bkt[gb0 + 1] = make_int2(0, 0);

    // ---- CTA reduction -> g_part ----
    #pragma unroll
    for (int o = 16; o; o >>= 1) {
        num += __shfl_xor_sync(0xffffffffu, num, o);
        den += __shfl_xor_sync(0xffffffffu, den, o);
    }
    if (lane == 0) { s_rn[w] = num; s_rd[w] = den; }
    __syncthreads();
    if (w == 0) {
        float n = s_rn[lane], d = s_rd[lane];
        #pragma unroll
        for (int o = 16; o; o >>= 1) {
            n += __shfl_xor_sync(0xffffffffu, n, o);
            d += __shfl_xor_sync(0xffffffffu, d, o);
        }
        if (lane == 0) g_part[blk] = make_float2(n, d);
    }

    CLUSTER_SYNC();                                     // HW barrier #2

    if (blk == 0 && w == 0) {                           // finalize
        float n = 0.f, d = 0.f;
        if (lane < NBLK) { float2 p = g_part[lane]; n = p.x; d = p.y; }
        #pragma unroll
        for (int o = 4; o; o >>= 1) {
            n += __shfl_xor_sync(0xffffffffu, n, o);
            d += __shfl_xor_sync(0xffffffffu, d, o);
        }
        if (lane == 0) out[0] = -n / d;
    }
    // rtot reset: all readers were pre-sync#2
    if (tid < BPC / 256)
        g_rtot[(blk * (BPC / 256) + tid) * RPAD] = 0.f;
}

extern "C" void kernel_launch(void* const* d_in, const int* in_sizes, int n_in,
                              void* d_out, int out_size) {
    const float* P_risk = (const float*)d_in[0];
    const float* T      = (const float*)d_in[1];
    const int*   E      = (const int*)d_in[2];
    float* out = (float*)d_out;

    k_all<<<NBLK, TPB>>>(P_risk, T, E, out);   // __cluster_dims__ applies cluster
}

// round 14
// speedup vs baseline: 2.6200x; 2.6200x over previous
#include <cuda_runtime.h>

// DeepSurvLoss, N=16384 — single kernel, ONE grid barrier (release/acquire).
// 32 blocks x 512 threads; block b owns buckets [b*512, (b+1)*512).
// bucket = floor(T*2^14): exact & monotone for T in [0,1).
// has_risk[i] <=> S_i > 0 exactly (all pe > 0; empty suffixes exact 0.0f).
//
// R14: R12 structure (64 SM-spread beats clusters) with: 32 arrivals instead
// of 64; red.release arrive + ld.acquire poll (no MEMBAR.ALL.GPU, no
// nanosleep); cnt atomic issued first (its return feeds the slot STG).

#define NB    16384
#define NBLK  32
#define TPB   512
#define RSHIFT 9                  // 512 buckets per block -> rtot counter id
#define CAP   16                  // slots per bucket (Poisson(1): safe)
#define RPAD  64                  // 256B stride per rtot counter
#define EPSF  1e-6f

struct __align__(256) Bucket {
    int    cnt;                   // byte 0
    float  bsum;                  // byte 4
    float2 slot[CAP];             // bytes 8..136 (slot[0..14] share line 0)
    int    pad[30];
};

__device__ Bucket   g_bkt[NB];               // headers reset by owner each call
__device__ __align__(256) float g_rtot[NBLK * RPAD];  // last block resets
__device__ float    g_num, g_den;            // last block resets
__device__ unsigned g_bar;
__device__ int      g_done;

__device__ __forceinline__ int bucket_of(float t) {
    int b = (int)(t * 16384.0f);             // *2^14: exact, order-preserving
    return b > (NB - 1) ? (NB - 1) : b;
}

__global__ void __launch_bounds__(TPB) k_all(const float* __restrict__ P_risk,
                                             const float* __restrict__ T,
                                             const int*   __restrict__ E,
                                             float* __restrict__ out) {
    __shared__ float s_suf[TPB];
    __shared__ float s_wf[16];
    __shared__ float s_rn[16], s_rd[16];
    __shared__ float s_above;
    __shared__ int   s_last;

    const int tid  = threadIdx.x, blk = blockIdx.x;
    const int lane = tid & 31,    w   = tid >> 5;
    const int i = blk * TPB + tid;

    // ---- Phase 1: one element per thread ----
    const float t_i  = T[i];
    const int   Ei   = E[i];
    const float pe_i = __expf(P_risk[i]);
    const int   b_i  = bucket_of(t_i);
    Bucket* bk = &g_bkt[b_i];
    const int pos = atomicAdd(&bk->cnt, 1);              // return feeds STG: first
    atomicAdd(&bk->bsum, pe_i);                          // line-private RED
    atomicAdd(&g_rtot[(b_i >> RSHIFT) * RPAD], pe_i);    // padded RED
    if (pos < CAP)
        bk->slot[pos] = make_float2(t_i, Ei ? -pe_i : pe_i);

    // ---- THE grid barrier (release arrive / acquire poll) ----
    __syncthreads();
    if (tid == 0) {
        asm volatile("red.release.gpu.global.add.u32 [%0], %1;"
                     :: "l"(&g_bar), "r"(1u) : "memory");
        unsigned v;
        do {
            asm volatile("ld.acquire.gpu.global.u32 %0, [%1];"
                         : "=r"(v) : "l"(&g_bar) : "memory");
        } while (v < NBLK);
    }
    __syncthreads();

    // ---- Phase 2: header LDG.64 (warms slot line) + s_above + suffix scan ----
    const int myb = (blk << RSHIFT) + tid;
    const int2 cb = *(const int2*)&g_bkt[myb];           // (cnt, bsum) bitcast
    int c = cb.x;  if (c > CAP) c = CAP;
    const float bs = __int_as_float(cb.y);
    if (w == 0) {                                        // s_above, lane-parallel
        float v = (lane > blk) ? g_rtot[lane * RPAD] : 0.f;
        #pragma unroll
        for (int o = 16; o; o >>= 1)
            v += __shfl_xor_sync(0xffffffffu, v, o);
        if (lane == 0) s_above = v;
    }
    s_suf[tid] = bs;
    __syncthreads();
    // exclusive scan over REVERSED bsum -> strictly-greater suffix per bucket
    const float f = s_suf[TPB - 1 - tid];
    float fs = f;
    #pragma unroll
    for (int o = 1; o < 32; o <<= 1) {
        float v = __shfl_up_sync(0xffffffffu, fs, o);
        if (lane >= o) fs += v;
    }
    if (lane == 31) s_wf[w] = fs;
    __syncthreads();
    if (tid == 0) {
        float a = 0.f;
        #pragma unroll
        for (int k = 0; k < 16; k++) { float v = s_wf[k]; s_wf[k] = a; a += v; }
    }
    __syncthreads();
    s_suf[TPB - 1 - tid] = s_wf[w] + (fs - f);
    __syncthreads();

    // ---- Phase 3: loss for my bucket's slots (slot line is L1-warm) ----
    float num = 0.f, den = 0.f;
    {
        const float suf = s_above + s_suf[tid];
        const float2* sl = g_bkt[myb].slot;
        for (int e1 = 0; e1 < c; e1++) {
            float2 v1 = sl[e1];
            if (v1.y < 0.f) {                            // E == 1
                float S = suf;
                for (int e2 = 0; e2 < c; e2++) {
                    if (e2 == e1) continue;
                    float2 v2 = sl[e2];
                    if (v2.x > v1.x) S += fabsf(v2.y);   // strict, exact
                }
                if (S > 0.f) {                           // has_risk (exact)
                    float pt = -v1.y / (S + EPSF);
                    num += __logf(fmaxf(pt, EPSF));      // upper clip: no-op
                    den += 1.f;
                }
            }
        }
    }
    // owner resets its own bucket header (only owner ever reads it)
    *(int2*)&g_bkt[myb] = make_int2(0, 0);

    // ---- block + grid reduction ----
    #pragma unroll
    for (int o = 16; o; o >>= 1) {
        num += __shfl_xor_sync(0xffffffffu, num, o);
        den += __shfl_xor_sync(0xffffffffu, den, o);
    }
    if (lane == 0) { s_rn[w] = num; s_rd[w] = den; }
    __syncthreads();
    if (tid == 0) {
        float n = 0.f, d = 0.f;
        #pragma unroll
        for (int k = 0; k < 16; k++) { n += s_rn[k]; d += s_rd[k]; }
        atomicAdd(&g_num, n);
        atomicAdd(&g_den, d);
        __threadfence();
        if (atomicAdd(&g_done, 1) == NBLK - 1) {         // last block
            float tn = atomicAdd(&g_num, 0.f);
            float td = atomicAdd(&g_den, 0.f);
            out[0] = -tn / td;
            g_num = 0.f; g_den = 0.f;
            g_done = 0; g_bar = 0u;
            s_last = 1;
        } else s_last = 0;
    }
    __syncthreads();
    if (s_last && tid < NBLK)                            // parallel rtot reset
        g_rtot[tid * RPAD] = 0.f;
}

extern "C" void kernel_launch(void* const* d_in, const int* in_sizes, int n_in,
                              void* d_out, int out_size) {
    const float* P_risk = (const float*)d_in[0];
    const float* T      = (const float*)d_in[1];
    const int*   E      = (const int*)d_in[2];
    float* out = (float*)d_out;

    k_all<<<NBLK, TPB>>>(P_risk, T, E, out);
}